// round 15
// baseline (speedup 1.0000x reference)
#include <cuda_runtime.h>
#include <math.h>

#define NMAX 200000
#define DD   256
#define BMAX 64
#define POOL_CHUNK 128
#define MSHIFT 75.0f
#define PSHIFT 70.0f

// ---------------- scratch (no allocations allowed) ----------------
__device__ float2 g_kv[2][NMAX];     // (k, v) packed per node
__device__ float  g_q[2][NMAX];
__device__ float2 g_sn[2][NMAX];     // (sum e, sum e*v*ms) per dst node
__device__ float  g_Sb[2][BMAX];
__device__ float  g_wsum[2];
__device__ float  g_kabs[2];         // max-accumulators (>=0); stale value is idempotent
__device__ float  g_vabs[2];

__device__ __forceinline__ void atomicMaxF(float* addr, float val) {
    if (val >= 0.0f) atomicMax((int*)addr, __float_as_int(val));
    else             atomicMin((unsigned int*)addr, __float_as_uint(val));
}

__device__ __forceinline__ void redAddF2(float2* addr, float a, float b) {
    unsigned long long p = (unsigned long long)__cvta_generic_to_global((void*)addr);
    asm volatile("red.global.add.v2.f32 [%0], {%1, %2};" :: "l"(p), "f"(a), "f"(b) : "memory");
}

// streaming int4 load that does not allocate in L1 (keeps L1 for gathers)
__device__ __forceinline__ int4 ldg_stream_int4(const int* p) {
    int4 v;
    asm("ld.global.nc.L1::no_allocate.v4.s32 {%0,%1,%2,%3}, [%4];"
        : "=r"(v.x), "=r"(v.y), "=r"(v.z), "=r"(v.w) : "l"(p));
    return v;
}

// ---------------- kqv: prologue does all per-run init; 4 nodes per warp iter ----------------
__global__ void __launch_bounds__(256, 3)
kqv_kernel(const float* __restrict__ xi, const float* __restrict__ xn,
           const float* __restrict__ Wi, const float* __restrict__ Wn,
           const float* __restrict__ bI, const float* __restrict__ bN,
           const float* __restrict__ wvi, const float* __restrict__ wvn,
           int Ni, int Nn) {
    int g = blockIdx.y;

    // ---- per-run init (idempotent; consumed only by later kernels) ----
    {
        int i = blockIdx.x * blockDim.x + threadIdx.x;
        int stride = gridDim.x * blockDim.x;
        float2 zero2 = make_float2(0.0f, 0.0f);
        for (int j = i; j < NMAX; j += stride) g_sn[g][j] = zero2;
        if (blockIdx.x == 0 && threadIdx.x < BMAX) {
            g_Sb[g][threadIdx.x] = 0.0f;
        }
        if (blockIdx.x == 0) {  // wsum reduction for this graph
            const float* w = g ? wvn : wvi;
            __shared__ float shw[8];
            float v = w[threadIdx.x];
            #pragma unroll
            for (int o = 16; o; o >>= 1) v += __shfl_xor_sync(0xffffffffu, v, o);
            if ((threadIdx.x & 31) == 0) shw[threadIdx.x >> 5] = v;
            __syncthreads();
            if (threadIdx.x == 0) {
                float t = 0.0f;
                #pragma unroll
                for (int j = 0; j < 8; j++) t += shw[j];
                g_wsum[g] = t;
            }
        }
    }

    const float* __restrict__ x = g ? xn : xi;
    const float* __restrict__ W = g ? Wn : Wi;
    const float* __restrict__ bb = g ? bN : bI;
    int N = g ? Nn : Ni;

    int gtid = blockIdx.x * blockDim.x + threadIdx.x;
    int warp = gtid >> 5, lane = gtid & 31;
    int nwarps = (gridDim.x * blockDim.x) >> 5;

    float wk[8], wq[8], wv[8];
    #pragma unroll
    for (int i = 0; i < 2; i++) {
        #pragma unroll
        for (int c = 0; c < 4; c++) {
            int d = (lane + 32 * i) * 4 + c;
            wk[i * 4 + c] = W[d * 3 + 0];
            wq[i * 4 + c] = W[d * 3 + 1];
            wv[i * 4 + c] = W[d * 3 + 2];
        }
    }
    float b0 = bb[0], b1 = bb[1], b2 = bb[2];
    float kabs = 0.0f, vabs = 0.0f;

    for (int n = warp * 4; n < N; n += nwarps * 4) {
        int nn[4];
        #pragma unroll
        for (int j = 0; j < 4; j++) nn[j] = min(n + j, N - 1);

        float4 lo[4], hi[4];
        #pragma unroll
        for (int j = 0; j < 4; j++) {
            const float4* xr = (const float4*)(x + (size_t)nn[j] * DD);
            lo[j] = __ldg(&xr[lane]);
            hi[j] = __ldg(&xr[lane + 32]);
        }

        float pk[4], pq[4], pv[4];
        #pragma unroll
        for (int j = 0; j < 4; j++) {
            float4 a = lo[j], c = hi[j];
            pk[j] = a.x*wk[0] + a.y*wk[1] + a.z*wk[2] + a.w*wk[3]
                  + c.x*wk[4] + c.y*wk[5] + c.z*wk[6] + c.w*wk[7];
            pq[j] = a.x*wq[0] + a.y*wq[1] + a.z*wq[2] + a.w*wq[3]
                  + c.x*wq[4] + c.y*wq[5] + c.z*wq[6] + c.w*wq[7];
            pv[j] = a.x*wv[0] + a.y*wv[1] + a.z*wv[2] + a.w*wv[3]
                  + c.x*wv[4] + c.y*wv[5] + c.z*wv[6] + c.w*wv[7];
        }

        #pragma unroll
        for (int o = 16; o; o >>= 1) {
            #pragma unroll
            for (int j = 0; j < 4; j++) {
                pk[j] += __shfl_xor_sync(0xffffffffu, pk[j], o);
                pq[j] += __shfl_xor_sync(0xffffffffu, pq[j], o);
                pv[j] += __shfl_xor_sync(0xffffffffu, pv[j], o);
            }
        }
        #pragma unroll
        for (int j = 0; j < 4; j++) {
            float kf = pk[j] + b0;
            float vf = pv[j] + b2;
            kabs = fmaxf(kabs, fabsf(kf));
            vabs = fmaxf(vabs, fabsf(vf));
            if (lane == 0) {
                g_kv[g][nn[j]] = make_float2(kf, vf);
                g_q[g][nn[j]]  = pq[j] + b1;
            }
        }
    }

    __shared__ float sm[8], sv[8];
    if (lane == 0) { sm[(threadIdx.x >> 5)] = kabs; sv[(threadIdx.x >> 5)] = vabs; }
    __syncthreads();
    if (threadIdx.x == 0) {
        float m = sm[0], v = sv[0];
        #pragma unroll
        for (int j = 1; j < 8; j++) { m = fmaxf(m, sm[j]); v = fmaxf(v, sv[j]); }
        atomicMaxF(&g_kabs[g], m);   // >=0; bss-zero first run, stale==final on replay
        atomicMaxF(&g_vabs[g], v);
    }
}

// ---------------- edge pass: e=exp(q*sc*k - (|q|C - 75)); red (S, N) ----------------
// Also zeroes d_out (runs before pool in stream order), replacing the memset.
__global__ void edge_sum_kernel(const int* __restrict__ ii, const int* __restrict__ ni,
                                const int* __restrict__ in_,
                                int Eii, int Eni, int Ein,
                                const float* aii, const float* pii, const float* mii,
                                const float* ani, const float* pni, const float* mni,
                                const float* ain, const float* pin_, const float* min_,
                                float* __restrict__ out) {
    int y = blockIdx.y;

    // zero d_out: first 32 blocks of y==0 (8192 float4 = 32K floats)
    {
        int i = blockIdx.x * blockDim.x + threadIdx.x;
        if (y == 0 && i < 2 * BMAX * DD / 4)
            ((float4*)out)[i] = make_float4(0.f, 0.f, 0.f, 0.f);
    }

    const int* __restrict__ ei; int E; const float2* __restrict__ kv;
    const float* __restrict__ q; float2* SN; float sc, ms, C;
    float Ki = g_kabs[0], Kn = g_kabs[1];
    float C0 = fmaxf(fabsf(aii[0] * pii[0]) * Ki, fabsf(ani[0] * pni[0]) * Kn);
    if (y == 0)      { ei = ii;  E = Eii; kv = g_kv[0]; q = g_q[0]; SN = g_sn[0]; sc = aii[0]*pii[0]; ms = mii[0]; C = C0; }
    else if (y == 1) { ei = ni;  E = Eni; kv = g_kv[1]; q = g_q[0]; SN = g_sn[0]; sc = ani[0]*pni[0]; ms = mni[0]; C = C0; }
    else             { ei = in_; E = Ein; kv = g_kv[0]; q = g_q[1]; SN = g_sn[1]; sc = ain[0]*pin_[0]; ms = min_[0]; C = fabsf(ain[0]*pin_[0]) * Ki; }

    bool vec4 = ((E & 3) == 0);
    int stride = gridDim.x * blockDim.x * 4;
    for (int e = (blockIdx.x * blockDim.x + threadIdx.x) * 4; e < E; e += stride) {
        if (e + 4 <= E) {
            int s0, s1, s2, s3, d0, d1, d2, d3;
            if (vec4) {
                int4 sv = ldg_stream_int4(ei + e);
                int4 dv = ldg_stream_int4(ei + E + e);
                s0 = sv.x; s1 = sv.y; s2 = sv.z; s3 = sv.w;
                d0 = dv.x; d1 = dv.y; d2 = dv.z; d3 = dv.w;
            } else {
                s0 = __ldg(ei + e);     s1 = __ldg(ei + e + 1);
                s2 = __ldg(ei + e + 2); s3 = __ldg(ei + e + 3);
                d0 = __ldg(ei + E + e);     d1 = __ldg(ei + E + e + 1);
                d2 = __ldg(ei + E + e + 2); d3 = __ldg(ei + E + e + 3);
            }
            float2 kv0 = __ldg(&kv[s0]), kv1 = __ldg(&kv[s1]);
            float2 kv2 = __ldg(&kv[s2]), kv3 = __ldg(&kv[s3]);
            float q0 = __ldg(&q[d0]), q1 = __ldg(&q[d1]);
            float q2 = __ldg(&q[d2]), q3 = __ldg(&q[d3]);
            float e0 = __expf(q0 * sc * kv0.x - (fabsf(q0) * C - MSHIFT));
            float e1 = __expf(q1 * sc * kv1.x - (fabsf(q1) * C - MSHIFT));
            float e2 = __expf(q2 * sc * kv2.x - (fabsf(q2) * C - MSHIFT));
            float e3 = __expf(q3 * sc * kv3.x - (fabsf(q3) * C - MSHIFT));
            redAddF2(&SN[d0], e0, e0 * kv0.y * ms);
            redAddF2(&SN[d1], e1, e1 * kv1.y * ms);
            redAddF2(&SN[d2], e2, e2 * kv2.y * ms);
            redAddF2(&SN[d3], e3, e3 * kv3.y * ms);
        } else {
            for (int t = e; t < E; t++) {
                int s = __ldg(ei + t), d = __ldg(ei + E + t);
                float2 kvv = __ldg(&kv[s]);
                float qv = __ldg(&q[d]);
                float ex = __expf(qv * sc * kvv.x - (fabsf(qv) * C - MSHIFT));
                redAddF2(&SN[d], ex, ex * kvv.y * ms);
            }
        }
    }
}

// ---------------- pooling: fused score+softmax-weight+stream; 64 thr, float4/thread ----------------
__global__ void __launch_bounds__(64, 20)
pool_kernel(const float* __restrict__ xi, const float* __restrict__ xn,
            const int* __restrict__ bti, const int* __restrict__ btn,
            int Ni, int Nn, float* __restrict__ out,
            const float* owi, const float* obi,
            const float* own, const float* obn,
            const float* bvi, const float* bvn,
            const float* mii, const float* mni, const float* min_) {
    int g = blockIdx.y;
    const float* __restrict__ x = g ? xn : xi;
    const int* __restrict__ batch = g ? btn : bti;
    int N = g ? Nn : Ni;
    float2* outg = (float2*)(out + (size_t)g * BMAX * DD);

    int start = blockIdx.x * POOL_CHUNK;
    if (start >= N) return;
    int len = min(POOL_CHUNK, N - start);

    // analytic shift: |agg| <= Amax; |score| <= B; M = B - PSHIFT
    float Vi = g_vabs[0], Vn = g_vabs[1];
    float Amax, ow, ob, boff;
    if (g == 0) {
        Amax = fmaxf(Vi * fabsf(mii[0]), Vn * fabsf(mni[0]));
        ow = owi[0]; ob = obi[0]; boff = (float)DD * bvi[0];
    } else {
        Amax = Vi * fabsf(min_[0]);
        ow = own[0]; ob = obn[0]; boff = (float)DD * bvn[0];
    }
    float wsum = g_wsum[g];
    float M = (Amax * fabsf(ow) + fabsf(ob)) * fabsf(wsum) + fabsf(boff) - PSHIFT;

    __shared__ float sw[POOL_CHUNK];
    __shared__ int sb[POOL_CHUNK];
    int t = threadIdx.x;                 // 0..63
    #pragma unroll
    for (int c = 0; c < POOL_CHUNK / 64; c++) {
        int idx = c * 64 + t;
        if (idx < len) {
            sb[idx] = batch[start + idx];
            float2 sn = g_sn[g][start + idx];
            float agg = sn.y / (sn.x + 1e-16f);
            float attn = 0.5f * agg * (1.0f + erff(agg * 0.70710678118654752f)) * ow + ob;
            float sc = attn * wsum + boff;
            sw[idx] = __expf(sc - M);
        }
    }
    __syncthreads();

    // thread t owns features [4t, 4t+4); node r's slice at xp + r*64 (float4 units)
    const float4* __restrict__ xp = (const float4*)(x + (size_t)start * DD) + t;

    if (sb[0] == sb[len - 1]) {
        // ---- fast path: whole chunk in one batch (~96% of blocks) ----
        int b = sb[0];
        float4 acc = make_float4(0.f, 0.f, 0.f, 0.f);
        float wl = 0.0f;
        const float4* __restrict__ p = xp;
        int r = 0;
        for (; r + 4 <= len; r += 4, p += 256) {
            float4 x0 = p[0];
            float4 x1 = p[64];
            float4 x2 = p[128];
            float4 x3 = p[192];
            float w0 = sw[r], w1 = sw[r + 1], w2 = sw[r + 2], w3 = sw[r + 3];
            acc.x += w0*x0.x + w1*x1.x + w2*x2.x + w3*x3.x;
            acc.y += w0*x0.y + w1*x1.y + w2*x2.y + w3*x3.y;
            acc.z += w0*x0.z + w1*x1.z + w2*x2.z + w3*x3.z;
            acc.w += w0*x0.w + w1*x1.w + w2*x2.w + w3*x3.w;
            wl += w0 + w1 + w2 + w3;
        }
        for (; r < len; ++r, p += 64) {
            float4 xv = p[0];
            float w0 = sw[r];
            acc.x += w0*xv.x; acc.y += w0*xv.y; acc.z += w0*xv.z; acc.w += w0*xv.w;
            wl += w0;
        }
        redAddF2(&outg[b * (DD/2) + t*2],     acc.x, acc.y);
        redAddF2(&outg[b * (DD/2) + t*2 + 1], acc.z, acc.w);
        if (t == 0) atomicAdd(&g_Sb[g][b], wl);
    } else {
        // ---- slow path: chunk spans a batch boundary (rare) ----
        int i = 0;
        while (i < len) {
            int b = sb[i];
            int j = i + 1;
            while (j < len && sb[j] == b) ++j;
            float4 acc = make_float4(0.f, 0.f, 0.f, 0.f);
            float wl = 0.0f;
            const float4* __restrict__ p = xp + i * 64;
            int r = i;
            for (; r + 4 <= j; r += 4, p += 256) {
                float4 x0 = p[0];
                float4 x1 = p[64];
                float4 x2 = p[128];
                float4 x3 = p[192];
                float w0 = sw[r], w1 = sw[r + 1], w2 = sw[r + 2], w3 = sw[r + 3];
                acc.x += w0*x0.x + w1*x1.x + w2*x2.x + w3*x3.x;
                acc.y += w0*x0.y + w1*x1.y + w2*x2.y + w3*x3.y;
                acc.z += w0*x0.z + w1*x1.z + w2*x2.z + w3*x3.z;
                acc.w += w0*x0.w + w1*x1.w + w2*x2.w + w3*x3.w;
                wl += w0 + w1 + w2 + w3;
            }
            for (; r < j; ++r, p += 64) {
                float4 xv = p[0];
                float w0 = sw[r];
                acc.x += w0*xv.x; acc.y += w0*xv.y; acc.z += w0*xv.z; acc.w += w0*xv.w;
                wl += w0;
            }
            redAddF2(&outg[b * (DD/2) + t*2],     acc.x, acc.y);
            redAddF2(&outg[b * (DD/2) + t*2 + 1], acc.z, acc.w);
            if (t == 0) atomicAdd(&g_Sb[g][b], wl);
            i = j;
        }
    }
}

// ---------------- final divide by Sb (float4-wide) ----------------
__global__ void final_div_kernel(float* __restrict__ out) {
    int idx = blockIdx.x * blockDim.x + threadIdx.x;   // 0..8191, one float4 each
    int row = idx >> 6;                                 // idx / (DD/4)
    float s = g_Sb[row >> 6][row & 63] + 1e-16f;
    float inv = 1.0f / s;
    float4* o = (float4*)out + idx;
    float4 v = *o;
    v.x *= inv; v.y *= inv; v.z *= inv; v.w *= inv;
    *o = v;
}

extern "C" void kernel_launch(void* const* d_in, const int* in_sizes, int n_in,
                              void* d_out, int out_size) {
    const float* x_i   = (const float*)d_in[0];
    const float* x_n   = (const float*)d_in[1];
    const int*   ei_ii = (const int*)d_in[2];
    const int*   ei_in = (const int*)d_in[3];
    const int*   ei_ni = (const int*)d_in[4];
    const int*   b_i   = (const int*)d_in[5];
    const int*   b_n   = (const int*)d_in[6];
    const float* Wi    = (const float*)d_in[7];
    const float* bi    = (const float*)d_in[8];
    const float* Wn    = (const float*)d_in[9];
    const float* bn    = (const float*)d_in[10];
    const float* a_ii  = (const float*)d_in[11];
    const float* m_ii  = (const float*)d_in[12];
    const float* p_ii  = (const float*)d_in[13];
    const float* a_in  = (const float*)d_in[14];
    const float* m_in  = (const float*)d_in[15];
    const float* p_in  = (const float*)d_in[16];
    const float* a_ni  = (const float*)d_in[17];
    const float* m_ni  = (const float*)d_in[18];
    const float* p_ni  = (const float*)d_in[19];
    const float* outw_i = (const float*)d_in[20];
    const float* outb_i = (const float*)d_in[21];
    const float* outw_n = (const float*)d_in[22];
    const float* outb_n = (const float*)d_in[23];
    const float* w_i    = (const float*)d_in[24];
    const float* bv_i   = (const float*)d_in[25];
    const float* w_n    = (const float*)d_in[26];
    const float* bv_n   = (const float*)d_in[27];

    int Ni  = in_sizes[0] / DD;
    int Nn  = in_sizes[1] / DD;
    int Eii = in_sizes[2] / 2;
    int Ein = in_sizes[3] / 2;
    int Eni = in_sizes[4] / 2;
    int Nmax = Ni > Nn ? Ni : Nn;

    float* out = (float*)d_out;

    kqv_kernel<<<dim3(1024, 2), 256>>>(x_i, x_n, Wi, Wn, bi, bn, w_i, w_n, Ni, Nn);

    edge_sum_kernel<<<dim3(1536, 3), 256>>>(ei_ii, ei_ni, ei_in, Eii, Eni, Ein,
                                            a_ii, p_ii, m_ii, a_ni, p_ni, m_ni,
                                            a_in, p_in, m_in, out);

    pool_kernel<<<dim3((Nmax + POOL_CHUNK - 1) / POOL_CHUNK, 2), 64>>>(
        x_i, x_n, b_i, b_n, Ni, Nn, out,
        outw_i, outb_i, outw_n, outb_n, bv_i, bv_n, m_ii, m_ni, m_in);

    final_div_kernel<<<32, 256>>>(out);
}

// round 16
// speedup vs baseline: 1.0597x; 1.0597x over previous
#include <cuda_runtime.h>
#include <math.h>

#define NMAX 200000
#define DD   256
#define BMAX 64
#define POOL_CHUNK 64
#define MSHIFT 75.0f
#define PSHIFT 70.0f

// ---------------- scratch (no allocations allowed) ----------------
__device__ float2 g_kv[2][NMAX];     // (k, v) packed per node
__device__ float  g_q[2][NMAX];
__device__ float2 g_sn[2][NMAX];     // (sum e, sum e*v*ms) per dst node
__device__ float  g_Sb[2][BMAX];
__device__ float  g_wsum[2];
__device__ float  g_kabs[2];         // max-accumulators (>=0); stale value is idempotent
__device__ float  g_vabs[2];

__device__ __forceinline__ void atomicMaxF(float* addr, float val) {
    if (val >= 0.0f) atomicMax((int*)addr, __float_as_int(val));
    else             atomicMin((unsigned int*)addr, __float_as_uint(val));
}

__device__ __forceinline__ void redAddF2(float2* addr, float a, float b) {
    unsigned long long p = (unsigned long long)__cvta_generic_to_global((void*)addr);
    asm volatile("red.global.add.v2.f32 [%0], {%1, %2};" :: "l"(p), "f"(a), "f"(b) : "memory");
}

// streaming int4 load that does not allocate in L1 (keeps L1 for gathers)
__device__ __forceinline__ int4 ldg_stream_int4(const int* p) {
    int4 v;
    asm("ld.global.nc.L1::no_allocate.v4.s32 {%0,%1,%2,%3}, [%4];"
        : "=r"(v.x), "=r"(v.y), "=r"(v.z), "=r"(v.w) : "l"(p));
    return v;
}

// streaming float4 load (zero-reuse x stream; keep L1 for output/red sectors)
__device__ __forceinline__ float4 ldg_stream_f4(const float4* p) {
    float4 v;
    asm("ld.global.nc.L1::no_allocate.v4.f32 {%0,%1,%2,%3}, [%4];"
        : "=f"(v.x), "=f"(v.y), "=f"(v.z), "=f"(v.w) : "l"(p));
    return v;
}

// ---------------- kqv: prologue does all per-run init; 4 nodes per warp iter ----------------
__global__ void __launch_bounds__(256, 3)
kqv_kernel(const float* __restrict__ xi, const float* __restrict__ xn,
           const float* __restrict__ Wi, const float* __restrict__ Wn,
           const float* __restrict__ bI, const float* __restrict__ bN,
           const float* __restrict__ wvi, const float* __restrict__ wvn,
           int Ni, int Nn) {
    int g = blockIdx.y;

    // ---- per-run init (idempotent; consumed only by later kernels) ----
    {
        int i = blockIdx.x * blockDim.x + threadIdx.x;
        int stride = gridDim.x * blockDim.x;
        float2 zero2 = make_float2(0.0f, 0.0f);
        for (int j = i; j < NMAX; j += stride) g_sn[g][j] = zero2;
        if (blockIdx.x == 0 && threadIdx.x < BMAX) {
            g_Sb[g][threadIdx.x] = 0.0f;
        }
        if (blockIdx.x == 0) {  // wsum reduction for this graph
            const float* w = g ? wvn : wvi;
            __shared__ float shw[8];
            float v = w[threadIdx.x];
            #pragma unroll
            for (int o = 16; o; o >>= 1) v += __shfl_xor_sync(0xffffffffu, v, o);
            if ((threadIdx.x & 31) == 0) shw[threadIdx.x >> 5] = v;
            __syncthreads();
            if (threadIdx.x == 0) {
                float t = 0.0f;
                #pragma unroll
                for (int j = 0; j < 8; j++) t += shw[j];
                g_wsum[g] = t;
            }
        }
    }

    const float* __restrict__ x = g ? xn : xi;
    const float* __restrict__ W = g ? Wn : Wi;
    const float* __restrict__ bb = g ? bN : bI;
    int N = g ? Nn : Ni;

    int gtid = blockIdx.x * blockDim.x + threadIdx.x;
    int warp = gtid >> 5, lane = gtid & 31;
    int nwarps = (gridDim.x * blockDim.x) >> 5;

    float wk[8], wq[8], wv[8];
    #pragma unroll
    for (int i = 0; i < 2; i++) {
        #pragma unroll
        for (int c = 0; c < 4; c++) {
            int d = (lane + 32 * i) * 4 + c;
            wk[i * 4 + c] = W[d * 3 + 0];
            wq[i * 4 + c] = W[d * 3 + 1];
            wv[i * 4 + c] = W[d * 3 + 2];
        }
    }
    float b0 = bb[0], b1 = bb[1], b2 = bb[2];
    float kabs = 0.0f, vabs = 0.0f;

    for (int n = warp * 4; n < N; n += nwarps * 4) {
        int nn[4];
        #pragma unroll
        for (int j = 0; j < 4; j++) nn[j] = min(n + j, N - 1);

        float4 lo[4], hi[4];
        #pragma unroll
        for (int j = 0; j < 4; j++) {
            const float4* xr = (const float4*)(x + (size_t)nn[j] * DD);
            lo[j] = __ldg(&xr[lane]);
            hi[j] = __ldg(&xr[lane + 32]);
        }

        float pk[4], pq[4], pv[4];
        #pragma unroll
        for (int j = 0; j < 4; j++) {
            float4 a = lo[j], c = hi[j];
            pk[j] = a.x*wk[0] + a.y*wk[1] + a.z*wk[2] + a.w*wk[3]
                  + c.x*wk[4] + c.y*wk[5] + c.z*wk[6] + c.w*wk[7];
            pq[j] = a.x*wq[0] + a.y*wq[1] + a.z*wq[2] + a.w*wq[3]
                  + c.x*wq[4] + c.y*wq[5] + c.z*wq[6] + c.w*wq[7];
            pv[j] = a.x*wv[0] + a.y*wv[1] + a.z*wv[2] + a.w*wv[3]
                  + c.x*wv[4] + c.y*wv[5] + c.z*wv[6] + c.w*wv[7];
        }

        #pragma unroll
        for (int o = 16; o; o >>= 1) {
            #pragma unroll
            for (int j = 0; j < 4; j++) {
                pk[j] += __shfl_xor_sync(0xffffffffu, pk[j], o);
                pq[j] += __shfl_xor_sync(0xffffffffu, pq[j], o);
                pv[j] += __shfl_xor_sync(0xffffffffu, pv[j], o);
            }
        }
        #pragma unroll
        for (int j = 0; j < 4; j++) {
            float kf = pk[j] + b0;
            float vf = pv[j] + b2;
            kabs = fmaxf(kabs, fabsf(kf));
            vabs = fmaxf(vabs, fabsf(vf));
            if (lane == 0) {
                g_kv[g][nn[j]] = make_float2(kf, vf);
                g_q[g][nn[j]]  = pq[j] + b1;
            }
        }
    }

    __shared__ float sm[8], sv[8];
    if (lane == 0) { sm[(threadIdx.x >> 5)] = kabs; sv[(threadIdx.x >> 5)] = vabs; }
    __syncthreads();
    if (threadIdx.x == 0) {
        float m = sm[0], v = sv[0];
        #pragma unroll
        for (int j = 1; j < 8; j++) { m = fmaxf(m, sm[j]); v = fmaxf(v, sv[j]); }
        atomicMaxF(&g_kabs[g], m);   // >=0; bss-zero first run, stale==final on replay
        atomicMaxF(&g_vabs[g], v);
    }
}

// ---------------- edge pass: e=exp(q*sc*k - (|q|C - 75)); red (S, N) ----------------
// Also zeroes d_out (runs before pool in stream order), replacing the memset.
__global__ void edge_sum_kernel(const int* __restrict__ ii, const int* __restrict__ ni,
                                const int* __restrict__ in_,
                                int Eii, int Eni, int Ein,
                                const float* aii, const float* pii, const float* mii,
                                const float* ani, const float* pni, const float* mni,
                                const float* ain, const float* pin_, const float* min_,
                                float* __restrict__ out) {
    int y = blockIdx.y;

    // zero d_out: first 32 blocks of y==0 (8192 float4 = 32K floats)
    {
        int i = blockIdx.x * blockDim.x + threadIdx.x;
        if (y == 0 && i < 2 * BMAX * DD / 4)
            ((float4*)out)[i] = make_float4(0.f, 0.f, 0.f, 0.f);
    }

    const int* __restrict__ ei; int E; const float2* __restrict__ kv;
    const float* __restrict__ q; float2* SN; float sc, ms, C;
    float Ki = g_kabs[0], Kn = g_kabs[1];
    float C0 = fmaxf(fabsf(aii[0] * pii[0]) * Ki, fabsf(ani[0] * pni[0]) * Kn);
    if (y == 0)      { ei = ii;  E = Eii; kv = g_kv[0]; q = g_q[0]; SN = g_sn[0]; sc = aii[0]*pii[0]; ms = mii[0]; C = C0; }
    else if (y == 1) { ei = ni;  E = Eni; kv = g_kv[1]; q = g_q[0]; SN = g_sn[0]; sc = ani[0]*pni[0]; ms = mni[0]; C = C0; }
    else             { ei = in_; E = Ein; kv = g_kv[0]; q = g_q[1]; SN = g_sn[1]; sc = ain[0]*pin_[0]; ms = min_[0]; C = fabsf(ain[0]*pin_[0]) * Ki; }

    bool vec4 = ((E & 3) == 0);
    int stride = gridDim.x * blockDim.x * 4;
    for (int e = (blockIdx.x * blockDim.x + threadIdx.x) * 4; e < E; e += stride) {
        if (e + 4 <= E) {
            int s0, s1, s2, s3, d0, d1, d2, d3;
            if (vec4) {
                int4 sv = ldg_stream_int4(ei + e);
                int4 dv = ldg_stream_int4(ei + E + e);
                s0 = sv.x; s1 = sv.y; s2 = sv.z; s3 = sv.w;
                d0 = dv.x; d1 = dv.y; d2 = dv.z; d3 = dv.w;
            } else {
                s0 = __ldg(ei + e);     s1 = __ldg(ei + e + 1);
                s2 = __ldg(ei + e + 2); s3 = __ldg(ei + e + 3);
                d0 = __ldg(ei + E + e);     d1 = __ldg(ei + E + e + 1);
                d2 = __ldg(ei + E + e + 2); d3 = __ldg(ei + E + e + 3);
            }
            float2 kv0 = __ldg(&kv[s0]), kv1 = __ldg(&kv[s1]);
            float2 kv2 = __ldg(&kv[s2]), kv3 = __ldg(&kv[s3]);
            float q0 = __ldg(&q[d0]), q1 = __ldg(&q[d1]);
            float q2 = __ldg(&q[d2]), q3 = __ldg(&q[d3]);
            float e0 = __expf(q0 * sc * kv0.x - (fabsf(q0) * C - MSHIFT));
            float e1 = __expf(q1 * sc * kv1.x - (fabsf(q1) * C - MSHIFT));
            float e2 = __expf(q2 * sc * kv2.x - (fabsf(q2) * C - MSHIFT));
            float e3 = __expf(q3 * sc * kv3.x - (fabsf(q3) * C - MSHIFT));
            redAddF2(&SN[d0], e0, e0 * kv0.y * ms);
            redAddF2(&SN[d1], e1, e1 * kv1.y * ms);
            redAddF2(&SN[d2], e2, e2 * kv2.y * ms);
            redAddF2(&SN[d3], e3, e3 * kv3.y * ms);
        } else {
            for (int t = e; t < E; t++) {
                int s = __ldg(ei + t), d = __ldg(ei + E + t);
                float2 kvv = __ldg(&kv[s]);
                float qv = __ldg(&q[d]);
                float ex = __expf(qv * sc * kvv.x - (fabsf(qv) * C - MSHIFT));
                redAddF2(&SN[d], ex, ex * kvv.y * ms);
            }
        }
    }
}

// ---------------- pooling: fused score+softmax-weight+stream; 64 thr, float4/thread ----------------
__global__ void __launch_bounds__(64, 20)
pool_kernel(const float* __restrict__ xi, const float* __restrict__ xn,
            const int* __restrict__ bti, const int* __restrict__ btn,
            int Ni, int Nn, float* __restrict__ out,
            const float* owi, const float* obi,
            const float* own, const float* obn,
            const float* bvi, const float* bvn,
            const float* mii, const float* mni, const float* min_) {
    int g = blockIdx.y;
    const float* __restrict__ x = g ? xn : xi;
    const int* __restrict__ batch = g ? btn : bti;
    int N = g ? Nn : Ni;
    float2* outg = (float2*)(out + (size_t)g * BMAX * DD);

    int start = blockIdx.x * POOL_CHUNK;
    if (start >= N) return;
    int len = min(POOL_CHUNK, N - start);

    // analytic shift: |agg| <= Amax; |score| <= B; M = B - PSHIFT
    float Vi = g_vabs[0], Vn = g_vabs[1];
    float Amax, ow, ob, boff;
    if (g == 0) {
        Amax = fmaxf(Vi * fabsf(mii[0]), Vn * fabsf(mni[0]));
        ow = owi[0]; ob = obi[0]; boff = (float)DD * bvi[0];
    } else {
        Amax = Vi * fabsf(min_[0]);
        ow = own[0]; ob = obn[0]; boff = (float)DD * bvn[0];
    }
    float wsum = g_wsum[g];
    float M = (Amax * fabsf(ow) + fabsf(ob)) * fabsf(wsum) + fabsf(boff) - PSHIFT;

    __shared__ float sw[POOL_CHUNK];
    __shared__ int sb[POOL_CHUNK];
    int t = threadIdx.x;                 // 0..63
    if (t < len) {
        sb[t] = batch[start + t];
        float2 sn = g_sn[g][start + t];
        float agg = sn.y / (sn.x + 1e-16f);
        float attn = 0.5f * agg * (1.0f + erff(agg * 0.70710678118654752f)) * ow + ob;
        float sc = attn * wsum + boff;
        sw[t] = __expf(sc - M);
    }
    __syncthreads();

    // thread t owns features [4t, 4t+4); node r's slice at xp + r*64 (float4 units)
    const float4* __restrict__ xp = (const float4*)(x + (size_t)start * DD) + t;

    if (sb[0] == sb[len - 1]) {
        // ---- fast path: whole chunk in one batch (~98% of blocks) ----
        int b = sb[0];
        float4 acc = make_float4(0.f, 0.f, 0.f, 0.f);
        float wl = 0.0f;
        const float4* __restrict__ p = xp;
        int r = 0;
        for (; r + 4 <= len; r += 4, p += 256) {
            float4 x0 = ldg_stream_f4(p);
            float4 x1 = ldg_stream_f4(p + 64);
            float4 x2 = ldg_stream_f4(p + 128);
            float4 x3 = ldg_stream_f4(p + 192);
            float w0 = sw[r], w1 = sw[r + 1], w2 = sw[r + 2], w3 = sw[r + 3];
            acc.x += w0*x0.x + w1*x1.x + w2*x2.x + w3*x3.x;
            acc.y += w0*x0.y + w1*x1.y + w2*x2.y + w3*x3.y;
            acc.z += w0*x0.z + w1*x1.z + w2*x2.z + w3*x3.z;
            acc.w += w0*x0.w + w1*x1.w + w2*x2.w + w3*x3.w;
            wl += w0 + w1 + w2 + w3;
        }
        for (; r < len; ++r, p += 64) {
            float4 xv = ldg_stream_f4(p);
            float w0 = sw[r];
            acc.x += w0*xv.x; acc.y += w0*xv.y; acc.z += w0*xv.z; acc.w += w0*xv.w;
            wl += w0;
        }
        redAddF2(&outg[b * (DD/2) + t*2],     acc.x, acc.y);
        redAddF2(&outg[b * (DD/2) + t*2 + 1], acc.z, acc.w);
        if (t == 0) atomicAdd(&g_Sb[g][b], wl);
    } else {
        // ---- slow path: chunk spans a batch boundary (rare) ----
        int i = 0;
        while (i < len) {
            int b = sb[i];
            int j = i + 1;
            while (j < len && sb[j] == b) ++j;
            float4 acc = make_float4(0.f, 0.f, 0.f, 0.f);
            float wl = 0.0f;
            const float4* __restrict__ p = xp + i * 64;
            for (int r = i; r < j; ++r, p += 64) {
                float4 xv = ldg_stream_f4(p);
                float w0 = sw[r];
                acc.x += w0*xv.x; acc.y += w0*xv.y; acc.z += w0*xv.z; acc.w += w0*xv.w;
                wl += w0;
            }
            redAddF2(&outg[b * (DD/2) + t*2],     acc.x, acc.y);
            redAddF2(&outg[b * (DD/2) + t*2 + 1], acc.z, acc.w);
            if (t == 0) atomicAdd(&g_Sb[g][b], wl);
            i = j;
        }
    }
}

// ---------------- final divide by Sb ----------------
__global__ void final_div_kernel(float* __restrict__ out) {
    int row = blockIdx.x;
    int graph = row >> 6, b = row & 63;
    out[(size_t)row * DD + threadIdx.x] /= (g_Sb[graph][b] + 1e-16f);
}

extern "C" void kernel_launch(void* const* d_in, const int* in_sizes, int n_in,
                              void* d_out, int out_size) {
    const float* x_i   = (const float*)d_in[0];
    const float* x_n   = (const float*)d_in[1];
    const int*   ei_ii = (const int*)d_in[2];
    const int*   ei_in = (const int*)d_in[3];
    const int*   ei_ni = (const int*)d_in[4];
    const int*   b_i   = (const int*)d_in[5];
    const int*   b_n   = (const int*)d_in[6];
    const float* Wi    = (const float*)d_in[7];
    const float* bi    = (const float*)d_in[8];
    const float* Wn    = (const float*)d_in[9];
    const float* bn    = (const float*)d_in[10];
    const float* a_ii  = (const float*)d_in[11];
    const float* m_ii  = (const float*)d_in[12];
    const float* p_ii  = (const float*)d_in[13];
    const float* a_in  = (const float*)d_in[14];
    const float* m_in  = (const float*)d_in[15];
    const float* p_in  = (const float*)d_in[16];
    const float* a_ni  = (const float*)d_in[17];
    const float* m_ni  = (const float*)d_in[18];
    const float* p_ni  = (const float*)d_in[19];
    const float* outw_i = (const float*)d_in[20];
    const float* outb_i = (const float*)d_in[21];
    const float* outw_n = (const float*)d_in[22];
    const float* outb_n = (const float*)d_in[23];
    const float* w_i    = (const float*)d_in[24];
    const float* bv_i   = (const float*)d_in[25];
    const float* w_n    = (const float*)d_in[26];
    const float* bv_n   = (const float*)d_in[27];

    int Ni  = in_sizes[0] / DD;
    int Nn  = in_sizes[1] / DD;
    int Eii = in_sizes[2] / 2;
    int Ein = in_sizes[3] / 2;
    int Eni = in_sizes[4] / 2;
    int Nmax = Ni > Nn ? Ni : Nn;

    float* out = (float*)d_out;

    kqv_kernel<<<dim3(1024, 2), 256>>>(x_i, x_n, Wi, Wn, bi, bn, w_i, w_n, Ni, Nn);

    edge_sum_kernel<<<dim3(1536, 3), 256>>>(ei_ii, ei_ni, ei_in, Eii, Eni, Ein,
                                            a_ii, p_ii, m_ii, a_ni, p_ni, m_ni,
                                            a_in, p_in, m_in, out);

    pool_kernel<<<dim3((Nmax + POOL_CHUNK - 1) / POOL_CHUNK, 2), 64>>>(
        x_i, x_n, b_i, b_n, Ni, Nn, out,
        outw_i, outb_i, outw_n, outb_n, bv_i, bv_n, m_ii, m_ni, m_in);

    final_div_kernel<<<2 * BMAX, 256>>>(out);
}